// round 6
// baseline (speedup 1.0000x reference)
#include <cuda_runtime.h>
#include <cstdint>

// Problem constants (fixed by the reference)
#define B_    64
#define T_    24
#define NV_   1024
#define C_    64
#define DPW_  7
#define TPD_  288
#define TILE_   (C_ * T_)        // 1536 floats = 6144 bytes per (b,n) slab
#define TILE4_  (TILE_ / 4)      // 384 float4
#define VPB_    32               // vertices per block
#define THREADS_ 128             // 4 warps -> 16 CTA/SM -> 64/64 warps (100% occ cap)
#define CHUNKS_  (TILE4_ / THREADS_)   // 3 float4 chunks per thread

__global__ __launch_bounds__(THREADS_)
void dte_kernel(const int* __restrict__ t,
                const float* __restrict__ W,
                float* __restrict__ out) {
    __shared__ float e[TILE_];
    __shared__ int dow_s[T_];
    __shared__ int tod_s[T_];

    const int b      = blockIdx.x >> 5;          // / (NV_/VPB_) == /32
    const int nchunk = blockIdx.x & 31;
    const int tid    = threadIdx.x;

    // Load the 24 (dow, tod) index pairs for this batch
    if (tid < T_) {
        int dow = t[(b * T_ + tid) * 2 + 0] % DPW_;
        int tod = t[(b * T_ + tid) * 2 + 1] % TPD_;
        dow_s[tid] = dow * C_;
        tod_s[tid] = (DPW_ + tod) * C_;
    }
    __syncthreads();

    // Build e[c][t] = W[dow_t][c] + W[DPW+tod_t][c]  (c-major, t-minor = output layout)
    #pragma unroll
    for (int idx = tid; idx < TILE_; idx += THREADS_) {
        int c  = idx / T_;
        int ti = idx - c * T_;
        e[idx] = W[dow_s[ti] + c] + W[tod_s[ti] + c];
    }
    __syncthreads();

    // Each thread owns CHUNKS_ float4s of the tile (stride THREADS_ for
    // warp-coalesced 128B lines), cached in registers.
    float4 val[CHUNKS_];
    #pragma unroll
    for (int k = 0; k < CHUNKS_; k++)
        val[k] = reinterpret_cast<const float4*>(e)[k * THREADS_ + tid];

    float4* o = reinterpret_cast<float4*>(
        out + ((size_t)b * NV_ + (size_t)nchunk * VPB_) * TILE_) + tid;

    #pragma unroll
    for (int v = 0; v < VPB_; v++) {
        #pragma unroll
        for (int k = 0; k < CHUNKS_; k++)
            o[(size_t)v * TILE4_ + k * THREADS_] = val[k];
    }
}

extern "C" void kernel_launch(void* const* d_in, const int* in_sizes, int n_in,
                              void* d_out, int out_size) {
    const int*   t = (const int*)d_in[0];    // [B, T, 2] int32
    const float* W = (const float*)d_in[1];  // [DPW+TPD, C] float32
    float* out = (float*)d_out;              // [B, N, C, T] float32

    dim3 grid(B_ * (NV_ / VPB_));            // 2048 blocks
    dte_kernel<<<grid, THREADS_>>>(t, W, out);
}

// round 7
// speedup vs baseline: 1.0738x; 1.0738x over previous
#include <cuda_runtime.h>
#include <cstdint>

// Problem constants (fixed by the reference)
#define B_    64
#define T_    24
#define NV_   1024
#define C_    64
#define DPW_  7
#define TPD_  288
#define TILE_   (C_ * T_)        // 1536 floats = 6144 bytes per (b,n) slab
#define TILE4_  (TILE_ / 4)      // 384 float4
#define VPB_    32               // vertices per block
#define THREADS_ 256             // 8 warps -> 8 CTA/SM residency = 64/64 warp cap
#define PAIR4_  (2 * TILE4_)     // 768 float4 across a pair of vertex slabs

__global__ __launch_bounds__(THREADS_)
void dte_kernel(const int* __restrict__ t,
                const float* __restrict__ W,
                float* __restrict__ out) {
    __shared__ float e[TILE_];
    __shared__ int dow_s[T_];
    __shared__ int tod_s[T_];

    const int b      = blockIdx.x >> 5;          // / (NV_/VPB_) == /32
    const int nchunk = blockIdx.x & 31;
    const int tid    = threadIdx.x;

    // Load the 24 (dow, tod) index pairs for this batch
    if (tid < T_) {
        int dow = t[(b * T_ + tid) * 2 + 0] % DPW_;
        int tod = t[(b * T_ + tid) * 2 + 1] % TPD_;
        dow_s[tid] = dow * C_;
        tod_s[tid] = (DPW_ + tod) * C_;
    }
    __syncthreads();

    // Build e[c][t] = W[dow_t][c] + W[DPW+tod_t][c]  (c-major, t-minor = output layout)
    #pragma unroll
    for (int idx = tid; idx < TILE_; idx += THREADS_) {
        int c  = idx / T_;
        int ti = idx - c * T_;
        e[idx] = W[dow_s[ti] + c] + W[tod_s[ti] + c];
    }
    __syncthreads();

    // Each thread owns 3 float4 positions within a 2-slab (pair) window:
    // flat pair-offsets tid, tid+256, tid+512; tile index is offset mod TILE4_.
    const float4* e4 = reinterpret_cast<const float4*>(e);
    const int f0 = tid, f1 = tid + THREADS_, f2 = tid + 2 * THREADS_;
    const float4 v0 = e4[f0 % TILE4_];
    const float4 v1 = e4[f1 % TILE4_];
    const float4 v2 = e4[f2 % TILE4_];

    float4* o = reinterpret_cast<float4*>(
        out + ((size_t)b * NV_ + (size_t)nchunk * VPB_) * TILE_);

    #pragma unroll
    for (int v = 0; v < VPB_; v += 2) {
        float4* p = o + (size_t)v * TILE4_;   // start of this vertex pair
        p[f0] = v0;
        p[f1] = v1;
        p[f2] = v2;
    }
}

extern "C" void kernel_launch(void* const* d_in, const int* in_sizes, int n_in,
                              void* d_out, int out_size) {
    const int*   t = (const int*)d_in[0];    // [B, T, 2] int32
    const float* W = (const float*)d_in[1];  // [DPW+TPD, C] float32
    float* out = (float*)d_out;              // [B, N, C, T] float32

    dim3 grid(B_ * (NV_ / VPB_));            // 2048 blocks
    dte_kernel<<<grid, THREADS_>>>(t, W, out);
}

// round 8
// speedup vs baseline: 1.0853x; 1.0107x over previous
#include <cuda_runtime.h>
#include <cstdint>

// Problem constants (fixed by the reference)
#define B_   64
#define T_   24
#define NV_  1024
#define C_   64
#define DPW_ 7
#define TPD_ 288
#define TILE_ (C_ * T_)          // 1536 floats = 6144 bytes per (b, n) slab
#define TILE4_ (TILE_ / 4)       // 384 float4
#define VPB_ 16                  // vertices per block -> 4096 blocks, ~5.5 waves
#define THREADS_ 384             // one float4 lane per thread

__global__ __launch_bounds__(THREADS_)
void dte_kernel(const int* __restrict__ t,
                const float* __restrict__ W,
                float* __restrict__ out) {
    __shared__ float e[TILE_];
    __shared__ int dow_s[T_];
    __shared__ int tod_s[T_];

    const int b      = blockIdx.x >> 6;          // / (NV_/VPB_) == /64
    const int nchunk = blockIdx.x & 63;
    const int tid    = threadIdx.x;

    // Load the 24 (dow, tod) index pairs for this batch
    if (tid < T_) {
        int dow = t[(b * T_ + tid) * 2 + 0] % DPW_;
        int tod = t[(b * T_ + tid) * 2 + 1] % TPD_;
        dow_s[tid] = dow * C_;
        tod_s[tid] = (DPW_ + tod) * C_;
    }
    __syncthreads();

    // Build e[c][t] = W[dow_t][c] + W[DPW+tod_t][c]  (c-major, t-minor = output layout)
    #pragma unroll
    for (int idx = tid; idx < TILE_; idx += THREADS_) {
        int c  = idx / T_;
        int ti = idx - c * T_;
        e[idx] = W[dow_s[ti] + c] + W[tod_s[ti] + c];
    }
    __syncthreads();

    // Each thread owns one float4 of the tile; broadcast to VPB_ vertices.
    const float4 val = reinterpret_cast<const float4*>(e)[tid];

    float4* o = reinterpret_cast<float4*>(
        out + ((size_t)b * NV_ + (size_t)nchunk * VPB_) * TILE_) + tid;

    #pragma unroll
    for (int v = 0; v < VPB_; v++) {
        o[(size_t)v * TILE4_] = val;
    }
}

extern "C" void kernel_launch(void* const* d_in, const int* in_sizes, int n_in,
                              void* d_out, int out_size) {
    const int*   t = (const int*)d_in[0];    // [B, T, 2] int32
    const float* W = (const float*)d_in[1];  // [DPW+TPD, C] float32
    float* out = (float*)d_out;              // [B, N, C, T] float32

    dim3 grid(B_ * (NV_ / VPB_));            // 4096 blocks
    dte_kernel<<<grid, THREADS_>>>(t, W, out);
}

// round 9
// speedup vs baseline: 1.1666x; 1.0749x over previous
#include <cuda_runtime.h>
#include <cstdint>

// Problem constants (fixed by the reference)
#define B_   64
#define T_   24
#define NV_  1024
#define C_   64
#define DPW_ 7
#define TPD_ 288
#define TILE_ (C_ * T_)          // 1536 floats = 6144 bytes per (b, n) slab
#define TILE4_ (TILE_ / 4)       // 384 float4
#define VERTS_PER_BLOCK_ 32
#define THREADS_ 384             // one float4 lane per thread

__global__ __launch_bounds__(THREADS_)
void dte_kernel(const int* __restrict__ t,
                const float* __restrict__ W,
                float* __restrict__ out) {
    __shared__ float e[TILE_];
    __shared__ int dow_s[T_];
    __shared__ int tod_s[T_];

    const int b      = blockIdx.x >> 5;          // / (NV_/VERTS_PER_BLOCK_) == /32
    const int nchunk = blockIdx.x & 31;
    const int tid    = threadIdx.x;

    // Load the 24 (dow, tod) index pairs for this batch
    if (tid < T_) {
        int dow = t[(b * T_ + tid) * 2 + 0] % DPW_;
        int tod = t[(b * T_ + tid) * 2 + 1] % TPD_;
        dow_s[tid] = dow * C_;
        tod_s[tid] = (DPW_ + tod) * C_;
    }
    __syncthreads();

    // Build e[c][t] = W[dow_t][c] + W[DPW+tod_t][c]  (c-major, t-minor = output layout)
    #pragma unroll
    for (int idx = tid; idx < TILE_; idx += THREADS_) {
        int c  = idx / T_;
        int ti = idx - c * T_;
        e[idx] = W[dow_s[ti] + c] + W[tod_s[ti] + c];
    }
    __syncthreads();

    // Each thread owns one float4 of the tile; broadcast to VERTS_PER_BLOCK_ vertices.
    const float4 val = reinterpret_cast<const float4*>(e)[tid];

    float4* o = reinterpret_cast<float4*>(
        out + ((size_t)b * NV_ + (size_t)nchunk * VERTS_PER_BLOCK_) * TILE_) + tid;

    #pragma unroll
    for (int v = 0; v < VERTS_PER_BLOCK_; v++) {
        o[(size_t)v * TILE4_] = val;
    }
}

extern "C" void kernel_launch(void* const* d_in, const int* in_sizes, int n_in,
                              void* d_out, int out_size) {
    const int*   t = (const int*)d_in[0];    // [B, T, 2] int32
    const float* W = (const float*)d_in[1];  // [DPW+TPD, C] float32
    float* out = (float*)d_out;              // [B, N, C, T] float32

    dim3 grid(B_ * (NV_ / VERTS_PER_BLOCK_));  // 2048 blocks
    dte_kernel<<<grid, THREADS_>>>(t, W, out);
}

// round 10
// speedup vs baseline: 1.1865x; 1.0171x over previous
#include <cuda_runtime.h>
#include <cstdint>

// Problem constants (fixed by the reference)
#define B_   64
#define T_   24
#define NV_  1024
#define C_   64
#define DPW_ 7
#define TPD_ 288
#define TILE_ (C_ * T_)          // 1536 floats = 6144 bytes per (b, n) slab
#define TILE4_ (TILE_ / 4)       // 384 float4
#define VERTS_PER_BLOCK_ 32
#define THREADS_ 384             // one float4 lane per thread

__global__ __launch_bounds__(THREADS_)
void dte_kernel(const int* __restrict__ t,
                const float* __restrict__ W,
                float* __restrict__ out) {
    __shared__ float e[TILE_];
    __shared__ int dow_s[T_];
    __shared__ int tod_s[T_];

    const int b      = blockIdx.x >> 5;          // / (NV_/VERTS_PER_BLOCK_) == /32
    const int nchunk = blockIdx.x & 31;
    const int tid    = threadIdx.x;

    // Load the 24 (dow, tod) index pairs for this batch
    if (tid < T_) {
        int dow = t[(b * T_ + tid) * 2 + 0] % DPW_;
        int tod = t[(b * T_ + tid) * 2 + 1] % TPD_;
        dow_s[tid] = dow * C_;
        tod_s[tid] = (DPW_ + tod) * C_;
    }
    __syncthreads();

    // Build e[c][t] = W[dow_t][c] + W[DPW+tod_t][c]  (c-major, t-minor = output layout)
    #pragma unroll
    for (int idx = tid; idx < TILE_; idx += THREADS_) {
        int c  = idx / T_;
        int ti = idx - c * T_;
        e[idx] = W[dow_s[ti] + c] + W[tod_s[ti] + c];
    }
    __syncthreads();

    // Each thread owns one float4 of the tile; broadcast to VERTS_PER_BLOCK_
    // vertices with streaming (evict-first) 128-bit stores.
    const float4 val = reinterpret_cast<const float4*>(e)[tid];

    float* o = out + ((size_t)b * NV_ + (size_t)nchunk * VERTS_PER_BLOCK_) * TILE_
                   + (size_t)tid * 4;

    #pragma unroll
    for (int v = 0; v < VERTS_PER_BLOCK_; v++) {
        asm volatile(
            "st.global.cs.v4.f32 [%0], {%1,%2,%3,%4};"
            :: "l"(o + (size_t)v * TILE_),
               "f"(val.x), "f"(val.y), "f"(val.z), "f"(val.w)
            : "memory");
    }
}

extern "C" void kernel_launch(void* const* d_in, const int* in_sizes, int n_in,
                              void* d_out, int out_size) {
    const int*   t = (const int*)d_in[0];    // [B, T, 2] int32
    const float* W = (const float*)d_in[1];  // [DPW+TPD, C] float32
    float* out = (float*)d_out;              // [B, N, C, T] float32

    dim3 grid(B_ * (NV_ / VERTS_PER_BLOCK_));  // 2048 blocks
    dte_kernel<<<grid, THREADS_>>>(t, W, out);
}